// round 1
// baseline (speedup 1.0000x reference)
#include <cuda_runtime.h>
#include <math_constants.h>

#define NMAX 50000
#define EMAX 800000

// ---------------- device scratch (no allocations allowed) ----------------
__device__ float g_h[NMAX * 128];      // current node features
__device__ float g_q[NMAX * 128];
__device__ float g_k[NMAX * 128];
__device__ float g_v[NMAX * 128];
__device__ float g_skip[NMAX * 128];
__device__ float g_h2[NMAX * 128];     // conv output (pre-LN)
__device__ float g_qe[NMAX * 16];      // q @ We^T
__device__ int   g_rowptr[NMAX + 1];
__device__ int   g_wp[NMAX + 1];       // histogram counters / write pointers
__device__ int   g_ssrc[EMAX];         // src sorted by dst
__device__ int   g_seid[EMAX];         // original edge id sorted by dst
__device__ float g_sea[EMAX * 16];     // edge_attr permuted into dst order
__device__ float g_red[2];             // LN sum / sumsq

// ---------------- sorting (counting sort by dst) ----------------
__global__ void k_zero_cnt(int n) {
    int i = blockIdx.x * blockDim.x + threadIdx.x;
    if (i <= n) g_wp[i] = 0;
}

__global__ void k_hist(const int* __restrict__ ei, int E) {
    int i = blockIdx.x * blockDim.x + threadIdx.x;
    if (i < E) atomicAdd(&g_wp[ei[E + i]], 1);
}

// single-block sequential-chunk Hillis-Steele scan over N counters
__global__ void k_scan(int n) {
    __shared__ int sdata[1024];
    __shared__ int s_carry;
    int tid = threadIdx.x;
    if (tid == 0) s_carry = 0;
    __syncthreads();
    for (int base = 0; base < n; base += 1024) {
        int i = base + tid;
        int v = (i < n) ? g_wp[i] : 0;
        sdata[tid] = v;
        __syncthreads();
        for (int off = 1; off < 1024; off <<= 1) {
            int t = (tid >= off) ? sdata[tid - off] : 0;
            __syncthreads();
            sdata[tid] += t;
            __syncthreads();
        }
        int excl = sdata[tid] - v + s_carry;
        if (i < n) { g_rowptr[i] = excl; g_wp[i] = excl; }
        __syncthreads();
        if (tid == 1023) s_carry += sdata[1023];
        __syncthreads();
    }
    if (tid == 0) g_rowptr[n] = s_carry;
}

__global__ void k_scatter(const int* __restrict__ ei, int E) {
    int i = blockIdx.x * blockDim.x + threadIdx.x;
    if (i < E) {
        int d = ei[E + i];
        int pos = atomicAdd(&g_wp[d], 1);
        g_ssrc[pos] = ei[i];
        g_seid[pos] = i;
    }
}

__global__ void k_gather_ea(const float* __restrict__ ea, int E) {
    int i = blockIdx.x * blockDim.x + threadIdx.x;
    if (i < E * 16) {
        int p = i >> 4, f = i & 15;
        g_sea[i] = ea[g_seid[p] * 16 + f];
    }
}

// ---------------- fc1: h = x @ W1 + b1  (x:[N,64], W1:[64,128]) ----------------
__global__ void k_fc1(const float* __restrict__ x, const float* __restrict__ W,
                      const float* __restrict__ b, int N) {
    __shared__ float xs[8 * 64];
    int j = threadIdx.x;            // 128 threads, thread = output column
    int r0 = blockIdx.x * 8;
    for (int t = j; t < 8 * 64; t += 128) {
        int r = t >> 6, k = t & 63;
        xs[t] = (r0 + r < N) ? x[(r0 + r) * 64 + k] : 0.f;
    }
    __syncthreads();
    float bj = b[j];
    float acc[8];
#pragma unroll
    for (int r = 0; r < 8; r++) acc[r] = bj;
    for (int k = 0; k < 64; k++) {
        float w = W[k * 128 + j];
#pragma unroll
        for (int r = 0; r < 8; r++) acc[r] += xs[r * 64 + k] * w;
    }
#pragma unroll
    for (int r = 0; r < 8; r++)
        if (r0 + r < N) g_h[(r0 + r) * 128 + j] = acc[r];
}

// ---------------- node transforms: q,k,v,skip = h @ {Wq,Wk,Wv,Ws} + bias ----------------
__global__ void k_transform(const float* __restrict__ Wq, const float* __restrict__ bq,
                            const float* __restrict__ Wk, const float* __restrict__ bk,
                            const float* __restrict__ Wv, const float* __restrict__ bv,
                            const float* __restrict__ Ws, const float* __restrict__ bs,
                            int N) {
    __shared__ float hs[16 * 128];
    int j = threadIdx.x;            // 128 threads
    int r0 = blockIdx.x * 16;
    for (int t = j; t < 16 * 128; t += 128) {
        int r = t >> 7, k = t & 127;
        hs[t] = (r0 + r < N) ? g_h[(r0 + r) * 128 + k] : 0.f;
    }
    __syncthreads();
    const float* Wm[4] = {Wq, Wk, Wv, Ws};
    const float* bm[4] = {bq, bk, bv, bs};
    float* om[4];
    om[0] = g_q; om[1] = g_k; om[2] = g_v; om[3] = g_skip;
    for (int m = 0; m < 4; m++) {
        const float* W = Wm[m];
        float bj = bm[m][j];
        float acc[16];
#pragma unroll
        for (int r = 0; r < 16; r++) acc[r] = bj;
        for (int k = 0; k < 128; k++) {
            float w = W[k * 128 + j];
#pragma unroll
            for (int r = 0; r < 16; r++) acc[r] += hs[r * 128 + k] * w;
        }
        float* o = om[m];
#pragma unroll
        for (int r = 0; r < 16; r++)
            if (r0 + r < N) o[(r0 + r) * 128 + j] = acc[r];
    }
}

// ---------------- qe = q @ We^T  ([N,16]) ----------------
__global__ void k_qe(const float* __restrict__ We, int N) {
    __shared__ float sWe[16 * 128];
    int tid = threadIdx.x;          // 256 threads, warp per node
    for (int t = tid; t < 2048; t += 256) sWe[t] = We[t];
    __syncthreads();
    int warp = tid >> 5, lane = tid & 31;
    int node = blockIdx.x * 8 + warp;
    if (node >= N) return;
    const float* qr = &g_q[node * 128];
    float q0 = qr[lane], q1 = qr[lane + 32], q2 = qr[lane + 64], q3 = qr[lane + 96];
#pragma unroll
    for (int f = 0; f < 16; f++) {
        float p = q0 * sWe[f * 128 + lane] + q1 * sWe[f * 128 + lane + 32]
                + q2 * sWe[f * 128 + lane + 64] + q3 * sWe[f * 128 + lane + 96];
#pragma unroll
        for (int o = 16; o; o >>= 1) p += __shfl_xor_sync(0xffffffffu, p, o);
        if (lane == f) g_qe[node * 16 + f] = p;
    }
}

// ---------------- edge conv: warp per dst node, online softmax over its segment ----------------
__global__ void k_conv(const float* __restrict__ We, int N) {
    __shared__ float sWe[2048];       // 8 KB
    __shared__ float sEA[8 * 32 * 16];// 16 KB: per-warp ea chunk buffer
    __shared__ float sL[8 * 32];      // per-warp logits chunk
    int tid = threadIdx.x;            // 256 threads = 8 warps
    for (int t = tid; t < 2048; t += 256) sWe[t] = We[t];
    __syncthreads();
    int warp = tid >> 5, lane = tid & 31;
    int node = blockIdx.x * 8 + warp;
    if (node >= N) return;

    const float RS = 0.08838834764831845f;  // 1/sqrt(128)
    const float* qr = &g_q[node * 128];
    float q0 = qr[lane], q1 = qr[lane + 32], q2 = qr[lane + 64], q3 = qr[lane + 96];
    float qef = (lane < 16) ? g_qe[node * 16 + lane] : 0.f;
    int s0 = g_rowptr[node], s1 = g_rowptr[node + 1];

    float m = -CUDART_INF_F, ssum = 0.f, wea = 0.f;
    float a0 = 0.f, a1 = 0.f, a2 = 0.f, a3 = 0.f;
    float* ea_w = &sEA[warp * 512];
    float* l_w  = &sL[warp * 32];

    for (int c = s0; c < s1; c += 32) {
        int cn = min(32, s1 - c);
        // sweep 1: logits for this chunk
        for (int ii = 0; ii < cn; ii++) {
            int src = g_ssrc[c + ii];
            const float* kr = &g_k[src * 128];
            float d = q0 * kr[lane] + q1 * kr[lane + 32]
                    + q2 * kr[lane + 64] + q3 * kr[lane + 96];
            if (lane < 16) {
                float eav = g_sea[(c + ii) * 16 + lane];
                ea_w[ii * 16 + lane] = eav;
                d += qef * eav;
            }
#pragma unroll
            for (int o = 16; o; o >>= 1) d += __shfl_xor_sync(0xffffffffu, d, o);
            if (lane == 0) l_w[ii] = d * RS;
        }
        __syncwarp();
        // chunk max, online rescale
        float cm = (lane < cn) ? l_w[lane] : -CUDART_INF_F;
#pragma unroll
        for (int o = 16; o; o >>= 1) cm = fmaxf(cm, __shfl_xor_sync(0xffffffffu, cm, o));
        float mn = fmaxf(m, cm);
        float sc = expf(m - mn);   // m=-inf on first chunk -> sc=0, accumulators are 0
        ssum *= sc; a0 *= sc; a1 *= sc; a2 *= sc; a3 *= sc; wea *= sc;
        m = mn;
        // sweep 2: weights + v aggregation + weighted ea
        for (int ii = 0; ii < cn; ii++) {
            int src = g_ssrc[c + ii];
            float w = expf(l_w[ii] - m);
            ssum += w;
            const float* vr = &g_v[src * 128];
            a0 += w * vr[lane];      a1 += w * vr[lane + 32];
            a2 += w * vr[lane + 64]; a3 += w * vr[lane + 96];
            if (lane < 16) wea += w * ea_w[ii * 16 + lane];
        }
    }

    float inv = 1.f / (ssum + 1e-16f);
    // per-node: add (Sum_e w*ea) @ We to the aggregated v
    float e0 = 0.f, e1 = 0.f, e2 = 0.f, e3 = 0.f;
#pragma unroll
    for (int f = 0; f < 16; f++) {
        float wf = __shfl_sync(0xffffffffu, wea, f);
        e0 += wf * sWe[f * 128 + lane];      e1 += wf * sWe[f * 128 + lane + 32];
        e2 += wf * sWe[f * 128 + lane + 64]; e3 += wf * sWe[f * 128 + lane + 96];
    }
    int b = node * 128 + lane;
    g_h2[b]      = (a0 + e0) * inv + g_skip[b];
    g_h2[b + 32] = (a1 + e1) * inv + g_skip[b + 32];
    g_h2[b + 64] = (a2 + e2) * inv + g_skip[b + 64];
    g_h2[b + 96] = (a3 + e3) * inv + g_skip[b + 96];
}

// ---------------- graph LayerNorm (over ALL nodes x features) + ReLU ----------------
__global__ void k_zero2() { g_red[0] = 0.f; g_red[1] = 0.f; }

__global__ void k_lnred(int total) {
    float s = 0.f, s2 = 0.f;
    for (int i = blockIdx.x * blockDim.x + threadIdx.x; i < total;
         i += gridDim.x * blockDim.x) {
        float v = g_h2[i];
        s += v; s2 += v * v;
    }
#pragma unroll
    for (int o = 16; o; o >>= 1) {
        s  += __shfl_xor_sync(0xffffffffu, s, o);
        s2 += __shfl_xor_sync(0xffffffffu, s2, o);
    }
    __shared__ float sh[16];
    int lane = threadIdx.x & 31, warp = threadIdx.x >> 5;
    if (lane == 0) { sh[warp] = s; sh[warp + 8] = s2; }
    __syncthreads();
    if (warp == 0) {
        s  = (lane < 8) ? sh[lane] : 0.f;
        s2 = (lane < 8) ? sh[lane + 8] : 0.f;
#pragma unroll
        for (int o = 4; o; o >>= 1) {
            s  += __shfl_xor_sync(0xffffffffu, s, o);
            s2 += __shfl_xor_sync(0xffffffffu, s2, o);
        }
        if (lane == 0) {
            atomicAdd(&g_red[0], s);
            atomicAdd(&g_red[1], s2);
        }
    }
}

__global__ void k_lnapply(const float* __restrict__ w, const float* __restrict__ b, int N) {
    int i = blockIdx.x * blockDim.x + threadIdx.x;
    int total = N * 128;
    float inv = 1.f / (float)total;
    float mu  = g_red[0] * inv;
    float var = g_red[1] * inv - mu * mu;
    float rs  = rsqrtf(var + 1e-5f);
    if (i < total) {
        int d = i & 127;
        float v = (g_h2[i] - mu) * rs * w[d] + b[d];
        g_h[i] = fmaxf(v, 0.f);
    }
}

// ---------------- fc2: out = h @ w2 + b2  (w2:[128,1]) ----------------
__global__ void k_fc2(const float* __restrict__ W, const float* __restrict__ b,
                      float* __restrict__ out, int N) {
    int tid = threadIdx.x, warp = tid >> 5, lane = tid & 31;
    int node = blockIdx.x * 8 + warp;
    if (node >= N) return;
    const float* h = &g_h[node * 128];
    float p = h[lane] * W[lane] + h[lane + 32] * W[lane + 32]
            + h[lane + 64] * W[lane + 64] + h[lane + 96] * W[lane + 96];
#pragma unroll
    for (int o = 16; o; o >>= 1) p += __shfl_xor_sync(0xffffffffu, p, o);
    if (lane == 0) out[node] = p + b[0];
}

// ---------------- launch ----------------
extern "C" void kernel_launch(void* const* d_in, const int* in_sizes, int n_in,
                              void* d_out, int out_size) {
    const float* x      = (const float*)d_in[0];
    const int*   ei     = (const int*)d_in[1];
    const float* ea     = (const float*)d_in[2];
    const float* fc1_w  = (const float*)d_in[3];
    const float* fc1_b  = (const float*)d_in[4];
    const float* fc2_w  = (const float*)d_in[27];
    const float* fc2_b  = (const float*)d_in[28];

    int N = in_sizes[0] / 64;
    int E = in_sizes[1] / 2;
    float* out = (float*)d_out;

    // edge sort by dst (deterministic work every call)
    k_zero_cnt<<<(N + 256) / 256, 256>>>(N);
    k_hist<<<(E + 255) / 256, 256>>>(ei, E);
    k_scan<<<1, 1024>>>(N);
    k_scatter<<<(E + 255) / 256, 256>>>(ei, E);
    k_gather_ea<<<(E * 16 + 255) / 256, 256>>>(ea, E);

    k_fc1<<<(N + 7) / 8, 128>>>(x, fc1_w, fc1_b, N);

    for (int L = 0; L < 2; L++) {
        int base = 5 + L * 11;
        const float* Wq = (const float*)d_in[base + 0];
        const float* bq = (const float*)d_in[base + 1];
        const float* Wk = (const float*)d_in[base + 2];
        const float* bk = (const float*)d_in[base + 3];
        const float* Wv = (const float*)d_in[base + 4];
        const float* bv = (const float*)d_in[base + 5];
        const float* We = (const float*)d_in[base + 6];
        const float* Ws = (const float*)d_in[base + 7];
        const float* bs = (const float*)d_in[base + 8];
        const float* lw = (const float*)d_in[base + 9];
        const float* lb = (const float*)d_in[base + 10];

        k_transform<<<(N + 15) / 16, 128>>>(Wq, bq, Wk, bk, Wv, bv, Ws, bs, N);
        k_qe<<<(N + 7) / 8, 256>>>(We, N);
        k_conv<<<(N + 7) / 8, 256>>>(We, N);
        k_zero2<<<1, 1>>>();
        k_lnred<<<512, 256>>>(N * 128);
        k_lnapply<<<(N * 128 + 255) / 256, 256>>>(lw, lb, N);
    }

    k_fc2<<<(N + 7) / 8, 256>>>(fc2_w, fc2_b, out, N);
}